// round 2
// baseline (speedup 1.0000x reference)
#include <cuda_runtime.h>
#include <cuda_bf16.h>

// out[t, :] = W[x[t], :] + b   for t in [0, 8192), D = 2048
// x: int32 [8192] (JAX demotes int64->int32 without x64), W: f32 [50257, 2048], b: f32 [2048]
// Pure gather + broadcast add. HBM-bound: ~128 MiB total traffic.

#define D_MODEL 2048
#define TOKENS  8192

__global__ __launch_bounds__(256, 8)
void embed_gather_kernel(const int* __restrict__ x,
                         const float4* __restrict__ W4,
                         const float4* __restrict__ b4,
                         float4* __restrict__ out4) {
    const int t = blockIdx.x;                         // token index
    const long long row = (long long)x[t];            // vocab row (uniform per block)
    const float4* __restrict__ src = W4 + row * (D_MODEL / 4);
    float4* __restrict__ dst = out4 + (long long)t * (D_MODEL / 4);

    // 512 float4 per row, 256 threads -> 2 per thread (fully unrolled)
    const int i0 = threadIdx.x;
    const int i1 = threadIdx.x + 256;

    float4 v0 = src[i0];
    float4 v1 = src[i1];
    float4 bb0 = b4[i0];
    float4 bb1 = b4[i1];

    v0.x += bb0.x; v0.y += bb0.y; v0.z += bb0.z; v0.w += bb0.w;
    v1.x += bb1.x; v1.y += bb1.y; v1.z += bb1.z; v1.w += bb1.w;

    dst[i0] = v0;
    dst[i1] = v1;
}

extern "C" void kernel_launch(void* const* d_in, const int* in_sizes, int n_in,
                              void* d_out, int out_size) {
    const int*    x = (const int*)d_in[0];        // [4, 2048] int32
    const float4* W = (const float4*)d_in[1];     // [50257, 2048] f32
    const float4* b = (const float4*)d_in[2];     // [2048] f32
    float4* out = (float4*)d_out;                 // [4, 2048, 2048] f32

    embed_gather_kernel<<<TOKENS, 256>>>(x, W, b, out);
}